// round 12
// baseline (speedup 1.0000x reference)
#include <cuda_runtime.h>
#include <cuda_fp16.h>
#include <cstdint>

// ---------------- problem constants ----------------
#define BATCH   65536
#define NCH     4
#define MTOT    (BATCH*NCH)   // 262144 rows (sample-major, 4 channels interleaved)
#define NN      512
#define NL      8

// ---------------- GEMM tiling (R6 frozen: 2 CTAs/SM, 16 warps/SM) ---------------
#define BM      64
#define BN      256
#define BK      64
#define TPB     256
#define KTILES  (NN/BK)       // 8
#define NTILES  ((MTOT/BM)*(NN/BN))   // 8192
#define ASTRIDE 72            // halves per smem row (64 + 8 pad), 144B
#define ASTAGE  (BM*ASTRIDE*2)        // 9216 B
#define BSTAGE  (BN*ASTRIDE*2)        // 36864 B
#define STAGE_BYTES (ASTAGE+BSTAGE)   // 46080 B
#define SMEM_BYTES      (STAGE_BYTES*2)        // 92160 B
#define SMEM_BYTES_LAST (STAGE_BYTES*2 + 768)  // + head-reduction buffer

// ---------------- device scratch (no runtime allocation allowed) ----------------
__device__ __align__(256) __half g_actA[(size_t)MTOT * NN];   // 256 MB
__device__ __align__(256) __half g_actB[(size_t)MTOT * NN];   // 256 MB
__device__ __align__(256) __half g_Wt[(size_t)NL * NN * NN];  // W^T per layer, fp16
__device__ __align__(256) float  g_G[3 * NN * 3];             // curl-head matrix

// ---------------- PTX helpers (baseline compute_103 features ONLY) --------------
__device__ __forceinline__ uint32_t smem_u32(const void* p) {
    uint32_t a;
    asm("{ .reg .u64 t; cvta.to.shared.u64 t, %1; cvt.u32.u64 %0, t; }"
        : "=r"(a) : "l"(p));
    return a;
}

#define CP_ASYNC16(dst, src) \
    asm volatile("cp.async.cg.shared.global [%0], [%1], 16;" \
                 :: "r"(dst), "l"(src) : "memory")
#define CP_COMMIT() asm volatile("cp.async.commit_group;" ::: "memory")
#define CP_WAIT(n)  asm volatile("cp.async.wait_group %0;" :: "n"(n) : "memory")

#define LDM4(r0, r1, r2, r3, addr) \
    asm volatile("ldmatrix.sync.aligned.m8n8.x4.shared.b16 {%0,%1,%2,%3}, [%4];" \
                 : "=r"(r0), "=r"(r1), "=r"(r2), "=r"(r3) : "r"(addr))

#define MMA16816(d, a, b) \
    asm volatile("mma.sync.aligned.m16n8k16.row.col.f32.f16.f16.f32 " \
                 "{%0,%1,%2,%3}, {%4,%5,%6,%7}, {%8,%9}, {%0,%1,%2,%3};" \
                 : "+f"((d)[0]), "+f"((d)[1]), "+f"((d)[2]), "+f"((d)[3]) \
                 : "r"((a)[0]), "r"((a)[1]), "r"((a)[2]), "r"((a)[3]), \
                   "r"((b)[0]), "r"((b)[1]))

// ---------------- setup: embed + W^T transpose + out zero + curl matrix ---------
__global__ __launch_bounds__(256) void setup_kernel(const float* __restrict__ inputs,
                                                    const float* __restrict__ Brff,
                                                    const float* __restrict__ Ws,
                                                    const float* __restrict__ Wf,
                                                    const float* __restrict__ scale,
                                                    float* __restrict__ out) {
    __shared__ float bsm[4 * 256];
    __shared__ float xs[32 * 4];
    __shared__ float tile[32][33];
    const int tid = threadIdx.x;

    if (blockIdx.x >= 4288) {
        // ---- curl head matrix: G[c][k][3] ----
        const float s0 = scale[0], s1 = scale[1], s2 = scale[2], s3 = scale[3];
        for (int k = tid; k < NN; k += 256) {
            const float w0 = Wf[k * 4 + 0] * s0, w1 = Wf[k * 4 + 1] * s1;
            const float w2 = Wf[k * 4 + 2] * s2, w3 = Wf[k * 4 + 3] * s3;
            g_G[(0 * NN + k) * 3 + 0] = -w1;
            g_G[(0 * NN + k) * 3 + 1] =  w0;
            g_G[(0 * NN + k) * 3 + 2] =  w3;
            g_G[(1 * NN + k) * 3 + 0] =  w3;
            g_G[(1 * NN + k) * 3 + 1] = -w2;
            g_G[(1 * NN + k) * 3 + 2] =  w1;
            g_G[(2 * NN + k) * 3 + 0] =  w2;
            g_G[(2 * NN + k) * 3 + 1] =  w3;
            g_G[(2 * NN + k) * 3 + 2] = -w0;
        }
        return;
    }
    if (blockIdx.x >= 4096) {
        const int i = (blockIdx.x - 4096) * 1024 + tid * 4;   // < 196608
        *reinterpret_cast<float4*>(out + i) = make_float4(0.f, 0.f, 0.f, 0.f);
        return;
    }
    if (blockIdx.x >= 2048) {
        // ---- W^T transpose: g_Wt[l][n][k] = Ws[l][k][n] ----
        const int bid = blockIdx.x - 2048;
        const int l = bid >> 8;
        const int t = bid & 255;
        const int k0 = (t >> 4) * 32, n0 = (t & 15) * 32;
        const float* src = Ws + ((size_t)l << 18);
        const int r = tid >> 5, c = tid & 31;
#pragma unroll
        for (int p = 0; p < 4; p++)
            tile[r + p * 8][c] = src[(size_t)(k0 + r + p * 8) * NN + (n0 + c)];
        __syncthreads();
        __half* dst = g_Wt + ((size_t)l << 18);
#pragma unroll
        for (int p = 0; p < 4; p++)
            dst[(size_t)(n0 + r + p * 8) * NN + (k0 + c)] =
                __float2half_rn(tile[c][r + p * 8]);
        return;
    }

    // ---- embed: RFF + tangent seeding ----
#pragma unroll
    for (int t = 0; t < 4; t++) bsm[t * 256 + tid] = Brff[t * 256 + tid];
    if (tid < 128) xs[tid] = inputs[(size_t)blockIdx.x * 128 + tid];
    __syncthreads();

    const int j = tid;
    const float b0 = bsm[j], b1 = bsm[256 + j], b2 = bsm[512 + j], b3 = bsm[768 + j];
#pragma unroll 1
    for (int it = 0; it < 32; it++) {
        float z = xs[it * 4 + 0] * b0 + xs[it * 4 + 1] * b1 +
                  xs[it * 4 + 2] * b2 + xs[it * 4 + 3] * b3;
        float sz, cz;
        __sincosf(z, &sz, &cz);
        size_t base = ((size_t)blockIdx.x * 32 + it) * NCH * NN;
        g_actA[base + j]            = __float2half_rn(sz);
        g_actA[base + 256 + j]      = __float2half_rn(cz);
        g_actA[base + 1 * NN + j]        = __float2half_rn(cz * b1);
        g_actA[base + 1 * NN + 256 + j]  = __float2half_rn(-sz * b1);
        g_actA[base + 2 * NN + j]        = __float2half_rn(cz * b2);
        g_actA[base + 2 * NN + 256 + j]  = __float2half_rn(-sz * b2);
        g_actA[base + 3 * NN + j]        = __float2half_rn(cz * b3);
        g_actA[base + 3 * NN + 256 + j]  = __float2half_rn(-sz * b3);
    }
}

// ---------------- fragment load helpers ----------------
__device__ __forceinline__ void load_a_frag(uint32_t a[2][4], uint32_t aB,
                                            int wm, int ks, int a_r, int a_c) {
#pragma unroll
    for (int mt = 0; mt < 2; mt++) {
        const int row = wm + mt * 16 + a_r;
        const uint32_t ad = aB + (uint32_t)((row * ASTRIDE + ks * 16 + a_c) * 2);
        LDM4(a[mt][0], a[mt][1], a[mt][2], a[mt][3], ad);
    }
}

__device__ __forceinline__ void load_b_frag(uint32_t b[8][2], uint32_t bB,
                                            int wn, int ks, int b_r, int b_c) {
#pragma unroll
    for (int bp = 0; bp < 4; bp++) {
        const int row = wn + bp * 16 + b_r;
        const uint32_t bd = bB + (uint32_t)((row * ASTRIDE + ks * 16 + b_c) * 2);
        uint32_t r0, r1, r2, r3;
        LDM4(r0, r1, r2, r3, bd);
        b[bp * 2][0] = r0;     b[bp * 2][1] = r2;
        b[bp * 2 + 1][0] = r1; b[bp * 2 + 1][1] = r3;
    }
}

// ---------------- stage-0 issue for a tile (prologue / cross-tile prefetch) -----
__device__ __forceinline__ void issue_stage0(const __half* __restrict__ Ain,
                                             const __half* __restrict__ Wl,
                                             int m0, int n0, int lrow, int lseg,
                                             uint32_t adst, uint32_t bdst) {
    const __half* ap = Ain + (size_t)(m0 + lrow) * NN + lseg * 8;
    const __half* bp = Wl + (size_t)(n0 + lrow) * NN + lseg * 8;
    CP_ASYNC16(adst, ap);
    CP_ASYNC16(adst + 32u * (ASTRIDE * 2), ap + (size_t)32 * NN);
#pragma unroll
    for (int j = 0; j < 8; j++)
        CP_ASYNC16(bdst + (uint32_t)j * 32u * (ASTRIDE * 2),
                   bp + (size_t)j * 32 * NN);
}

// ---------------- shared GEMM mainloop w/ cross-tile prefetch --------------------
// Stage 0 of THIS tile must already be committed. At kt==7 issues stage 0 of the
// next tile (tile index tn, if tn < NTILES) into buffer 0.
__device__ __forceinline__ void gemm_mainloop_pf(
    float d[2][8][4], const __half* __restrict__ Ain,
    const __half* __restrict__ Wl, uint32_t sbase,
    int m0, int n0, int tn,
    int tid, int lane, int wm, int wn) {

    const int lrow = tid >> 3, lseg = tid & 7;
    const __half* aptr = Ain + (size_t)(m0 + lrow) * NN + lseg * 8;
    const uint32_t adst = sbase + (uint32_t)(lrow * (ASTRIDE * 2) + lseg * 16);
    const __half* bptrs = Wl + (size_t)(n0 + lrow) * NN + lseg * 8;
    const uint32_t bdst = sbase + ASTAGE + (uint32_t)(lrow * (ASTRIDE * 2) + lseg * 16);

    const int a_r = (lane & 15);
    const int a_c = (lane >> 4) * 8;
    const int b_r = (lane & 7) + (((lane >> 3) & 1) << 3);
    const int b_c = (lane >> 4) * 8;

    uint32_t afr[2][2][4];
    uint32_t bfr[2][8][2];

#pragma unroll
    for (int kt = 0; kt < KTILES; kt++) {
        CP_WAIT(0);
        __syncthreads();

        if (kt + 1 < KTILES) {
            const uint32_t so = ((kt + 1) & 1) * STAGE_BYTES;
            const size_t ko = (size_t)(kt + 1) * BK;
            CP_ASYNC16(adst + so, aptr + ko);
            CP_ASYNC16(adst + so + 32u * (ASTRIDE * 2), aptr + (size_t)32 * NN + ko);
#pragma unroll
            for (int j = 0; j < 8; j++)
                CP_ASYNC16(bdst + so + (uint32_t)j * 32u * (ASTRIDE * 2),
                           bptrs + (size_t)j * 32 * NN + ko);
        } else if (tn < NTILES) {
            // prefetch next tile's stage 0 into buffer 0 (kt=6 compute fenced above)
            issue_stage0(Ain, Wl, (tn >> 1) * BM, (tn & 1) * BN,
                         lrow, lseg, adst, bdst);
        }
        CP_COMMIT();

        const uint32_t aB = sbase + (kt & 1) * STAGE_BYTES;
        const uint32_t bB = aB + ASTAGE;

        load_a_frag(afr[0], aB, wm, 0, a_r, a_c);
        load_b_frag(bfr[0], bB, wn, 0, b_r, b_c);
#pragma unroll
        for (int ks = 0; ks < 4; ks++) {
            const int cur = ks & 1, nxt = cur ^ 1;
            if (ks < 3) {
                load_a_frag(afr[nxt], aB, wm, ks + 1, a_r, a_c);
                load_b_frag(bfr[nxt], bB, wn, ks + 1, b_r, b_c);
            }
#pragma unroll
            for (int mt = 0; mt < 2; mt++)
#pragma unroll
                for (int nt = 0; nt < 8; nt++)
                    MMA16816(d[mt][nt], afr[cur][mt], bfr[cur][nt]);
        }
    }
}

// ---------------- mid layers 0..6: persistent GEMM + sin/cos JVP epilogue -------
__global__ __launch_bounds__(TPB, 2)
void layer_mid(int flip, int layer,
               const float* __restrict__ bs, const float* __restrict__ alphas) {
    const __half* __restrict__ Ain  = flip ? g_actB : g_actA;
    __half* __restrict__       Aout = flip ? g_actA : g_actB;
    const __half* __restrict__ Wl   = g_Wt + (size_t)layer * NN * NN;

    extern __shared__ __align__(128) char smem[];
    const uint32_t sbase = smem_u32(smem);
    const int tid = threadIdx.x, lane = tid & 31, wid = tid >> 5;
    const int wm = (wid >> 2) * 32;
    const int wn = (wid & 3) * 64;
    const int step = gridDim.x;

    const float s = 1.0f + __ldg(alphas + layer);
    const float* __restrict__ bias = bs + layer * NN;
    const int chan = (lane >> 2) & 3;
    const int srclane = lane & ~12;

    // prologue: stage 0 of the first tile
    {
        const int t0 = blockIdx.x;
        const int lrow = tid >> 3, lseg = tid & 7;
        const uint32_t adst = sbase + (uint32_t)(lrow * (ASTRIDE * 2) + lseg * 16);
        const uint32_t bdst = sbase + ASTAGE + (uint32_t)(lrow * (ASTRIDE * 2) + lseg * 16);
        issue_stage0(Ain, Wl, (t0 >> 1) * BM, (t0 & 1) * BN, lrow, lseg, adst, bdst);
        CP_COMMIT();
    }

#pragma unroll 1
    for (int t = blockIdx.x; t < NTILES; t += step) {
        const int m0 = (t >> 1) * BM, n0 = (t & 1) * BN;

        float d[2][8][4];
#pragma unroll
        for (int mt = 0; mt < 2; mt++)
#pragma unroll
            for (int nt = 0; nt < 8; nt++)
#pragma unroll
                for (int j = 0; j < 4; j++) d[mt][nt][j] = 0.f;

        gemm_mainloop_pf(d, Ain, Wl, sbase, m0, n0, t + step, tid, lane, wm, wn);

#pragma unroll
        for (int mt = 0; mt < 2; mt++) {
            const int r = m0 + wm + mt * 16 + (lane >> 2);
#pragma unroll
            for (int nt = 0; nt < 8; nt++) {
                const int c = n0 + wn + nt * 8 + (lane & 3) * 2;
                const float b0 = __ldg(bias + c), b1 = __ldg(bias + c + 1);
                const float v0 = d[mt][nt][0], v1 = d[mt][nt][1];
                const float v2 = d[mt][nt][2], v3 = d[mt][nt][3];
                const float p0 = __shfl_sync(0xffffffffu, v0, srclane);
                const float p1 = __shfl_sync(0xffffffffu, v1, srclane);
                const float p2 = __shfl_sync(0xffffffffu, v2, srclane);
                const float p3 = __shfl_sync(0xffffffffu, v3, srclane);
                const float q0 = (p0 + b0) * s, q1 = (p1 + b1) * s;
                const float q2 = (p2 + b0) * s, q3 = (p3 + b1) * s;
                float o0, o1, o2, o3;
                if (chan == 0) {
                    o0 = __sinf(q0); o1 = __sinf(q1); o2 = __sinf(q2); o3 = __sinf(q3);
                } else {
                    o0 = s * v0 * __cosf(q0); o1 = s * v1 * __cosf(q1);
                    o2 = s * v2 * __cosf(q2); o3 = s * v3 * __cosf(q3);
                }
                *reinterpret_cast<__half2*>(Aout + (size_t)r * NN + c) =
                    __floats2half2_rn(o0, o1);
                *reinterpret_cast<__half2*>(Aout + (size_t)(r + 8) * NN + c) =
                    __floats2half2_rn(o2, o3);
            }
        }
    }
}

// ---------------- last layer 7: persistent GEMM + fused curl head ---------------
__global__ __launch_bounds__(TPB, 2)
void layer_last(int flip, int layer,
                const float* __restrict__ bs, const float* __restrict__ alphas,
                float* __restrict__ out) {
    const __half* __restrict__ Ain = flip ? g_actB : g_actA;
    const __half* __restrict__ Wl  = g_Wt + (size_t)layer * NN * NN;

    extern __shared__ __align__(128) char smem[];
    const uint32_t sbase = smem_u32(smem);
    float* sbuf = reinterpret_cast<float*>(smem + 2 * STAGE_BYTES);  // 64 rows x 3
    const int tid = threadIdx.x, lane = tid & 31, wid = tid >> 5;
    const int wm = (wid >> 2) * 32;
    const int wn = (wid & 3) * 64;
    const int step = gridDim.x;

    const float s = 1.0f + __ldg(alphas + layer);
    const float* __restrict__ bias = bs + layer * NN;
    const int chan = (lane >> 2) & 3;
    const int srclane = lane & ~12;
    const float* __restrict__ Gc =
        (chan > 0) ? (g_G + (size_t)(chan - 1) * NN * 3) : g_G;

    {
        const int t0 = blockIdx.x;
        const int lrow = tid >> 3, lseg = tid & 7;
        const uint32_t adst = sbase + (uint32_t)(lrow * (ASTRIDE * 2) + lseg * 16);
        const uint32_t bdst = sbase + ASTAGE + (uint32_t)(lrow * (ASTRIDE * 2) + lseg * 16);
        issue_stage0(Ain, Wl, (t0 >> 1) * BM, (t0 & 1) * BN, lrow, lseg, adst, bdst);
        CP_COMMIT();
    }

#pragma unroll 1
    for (int t = blockIdx.x; t < NTILES; t += step) {
        const int m0 = (t >> 1) * BM, n0 = (t & 1) * BN;

        float d[2][8][4];
#pragma unroll
        for (int mt = 0; mt < 2; mt++)
#pragma unroll
            for (int nt = 0; nt < 8; nt++)
#pragma unroll
                for (int j = 0; j < 4; j++) d[mt][nt][j] = 0.f;

        gemm_mainloop_pf(d, Ain, Wl, sbase, m0, n0, t + step, tid, lane, wm, wn);

        // ---- fused head: out += sum_k act_tangent * G ----
        __syncthreads();
        if (tid < 192) sbuf[tid] = 0.f;
        __syncthreads();

#pragma unroll
        for (int mt = 0; mt < 2; mt++) {
            float part[2][3] = {{0.f, 0.f, 0.f}, {0.f, 0.f, 0.f}};
#pragma unroll
            for (int nt = 0; nt < 8; nt++) {
                const int c = n0 + wn + nt * 8 + (lane & 3) * 2;
                const float b0 = __ldg(bias + c), b1 = __ldg(bias + c + 1);
                const float v0 = d[mt][nt][0], v1 = d[mt][nt][1];
                const float v2 = d[mt][nt][2], v3 = d[mt][nt][3];
                const float p0 = __shfl_sync(0xffffffffu, v0, srclane);
                const float p1 = __shfl_sync(0xffffffffu, v1, srclane);
                const float p2 = __shfl_sync(0xffffffffu, v2, srclane);
                const float p3 = __shfl_sync(0xffffffffu, v3, srclane);
                if (chan != 0) {
                    const float q0 = (p0 + b0) * s, q1 = (p1 + b1) * s;
                    const float q2 = (p2 + b0) * s, q3 = (p3 + b1) * s;
                    const float o0 = s * v0 * __cosf(q0);
                    const float o1 = s * v1 * __cosf(q1);
                    const float o2 = s * v2 * __cosf(q2);
                    const float o3 = s * v3 * __cosf(q3);
                    const float g00 = __ldg(Gc + (size_t)c * 3 + 0);
                    const float g01 = __ldg(Gc + (size_t)c * 3 + 1);
                    const float g02 = __ldg(Gc + (size_t)c * 3 + 2);
                    const float g10 = __ldg(Gc + (size_t)(c + 1) * 3 + 0);
                    const float g11 = __ldg(Gc + (size_t)(c + 1) * 3 + 1);
                    const float g12 = __ldg(Gc + (size_t)(c + 1) * 3 + 2);
                    part[0][0] += o0 * g00 + o1 * g10;
                    part[0][1] += o0 * g01 + o1 * g11;
                    part[0][2] += o0 * g02 + o1 * g12;
                    part[1][0] += o2 * g00 + o3 * g10;
                    part[1][1] += o2 * g01 + o3 * g11;
                    part[1][2] += o2 * g02 + o3 * g12;
                }
            }
#pragma unroll
            for (int off = 1; off <= 2; off <<= 1)
#pragma unroll
                for (int h = 0; h < 2; h++)
#pragma unroll
                    for (int j = 0; j < 3; j++)
                        part[h][j] += __shfl_xor_sync(0xffffffffu, part[h][j], off);
            if ((lane & 3) == 0 && chan != 0) {
                const int row0 = wm + mt * 16 + (lane >> 2);
#pragma unroll
                for (int j = 0; j < 3; j++) {
                    atomicAdd(sbuf + row0 * 3 + j, part[0][j]);
                    atomicAdd(sbuf + (row0 + 8) * 3 + j, part[1][j]);
                }
            }
        }
        __syncthreads();
        if (tid < 192) {
            const int row = tid / 3, j = tid - row * 3;
            if ((row & 3) != 0)
                atomicAdd(out + (size_t)((m0 + row) >> 2) * 3 + j, sbuf[row * 3 + j]);
        }
    }
}

// ---------------- host launcher ----------------
extern "C" void kernel_launch(void* const* d_in, const int* in_sizes, int n_in,
                              void* d_out, int out_size) {
    const float* inputs = (const float*)d_in[0];  // [65536,4]
    const float* Brff   = (const float*)d_in[1];  // [4,256]
    const float* Ws     = (const float*)d_in[2];  // [8,512,512]
    const float* bs     = (const float*)d_in[3];  // [8,512]
    const float* alphas = (const float*)d_in[4];  // [9]
    const float* Wf     = (const float*)d_in[5];  // [512,4]
    const float* scale  = (const float*)d_in[6];  // [4]
    float* out = (float*)d_out;                   // [65536,3]

    cudaFuncSetAttribute(layer_mid, cudaFuncAttributeMaxDynamicSharedMemorySize,
                         SMEM_BYTES);
    cudaFuncSetAttribute(layer_last, cudaFuncAttributeMaxDynamicSharedMemorySize,
                         SMEM_BYTES_LAST);

    int nsm = 148;
    cudaDeviceGetAttribute(&nsm, cudaDevAttrMultiProcessorCount, 0);
    const int pgrid = 2 * nsm;   // persistent CTAs: 2 per SM

    setup_kernel<<<4289, 256>>>(inputs, Brff, Ws, Wf, scale, out);
    for (int l = 0; l < NL - 1; l++)
        layer_mid<<<pgrid, TPB, SMEM_BYTES>>>(l & 1, l, bs, alphas);
    layer_last<<<pgrid, TPB, SMEM_BYTES_LAST>>>((NL - 1) & 1, NL - 1, bs, alphas, out);
}

// round 13
// speedup vs baseline: 1.0669x; 1.0669x over previous
#include <cuda_runtime.h>
#include <cuda_fp16.h>
#include <cstdint>

// ---------------- problem constants ----------------
#define BATCH   65536
#define NCH     4
#define MTOT    (BATCH*NCH)   // 262144 rows (sample-major, 4 channels interleaved)
#define NN      512
#define NL      8

// ---------------- GEMM tiling (R6 frozen: 2 CTAs/SM, 16 warps/SM) ---------------
#define BM      64
#define BN      256
#define BK      64
#define TPB     256
#define KTILES  (NN/BK)       // 8
#define ASTRIDE 72            // halves per smem row (64 + 8 pad), 144B
#define ASTAGE  (BM*ASTRIDE*2)        // 9216 B
#define BSTAGE  (BN*ASTRIDE*2)        // 36864 B
#define STAGE_BYTES (ASTAGE+BSTAGE)   // 46080 B
#define SMEM_BYTES  (STAGE_BYTES*2)   // 92160 B  (x2 CTAs = 184320 <= 227KB)

// ---------------- device scratch (no runtime allocation allowed) ----------------
__device__ __align__(256) __half g_actA[(size_t)MTOT * NN];   // 256 MB
__device__ __align__(256) __half g_actB[(size_t)MTOT * NN];   // 256 MB
__device__ __align__(256) __half g_Wt[(size_t)NL * NN * NN];  // W^T per layer, fp16
__device__ __align__(256) float  g_G[3 * NN * 3];             // curl-head matrix

// ---------------- PTX helpers (baseline compute_103 features ONLY) --------------
__device__ __forceinline__ uint32_t smem_u32(const void* p) {
    uint32_t a;
    asm("{ .reg .u64 t; cvta.to.shared.u64 t, %1; cvt.u32.u64 %0, t; }"
        : "=r"(a) : "l"(p));
    return a;
}

#define CP_ASYNC16(dst, src) \
    asm volatile("cp.async.cg.shared.global [%0], [%1], 16;" \
                 :: "r"(dst), "l"(src) : "memory")
#define CP_COMMIT() asm volatile("cp.async.commit_group;" ::: "memory")
#define CP_WAIT(n)  asm volatile("cp.async.wait_group %0;" :: "n"(n) : "memory")

#define LDM4(r0, r1, r2, r3, addr) \
    asm volatile("ldmatrix.sync.aligned.m8n8.x4.shared.b16 {%0,%1,%2,%3}, [%4];" \
                 : "=r"(r0), "=r"(r1), "=r"(r2), "=r"(r3) : "r"(addr))

#define MMA16816(d, a, b) \
    asm volatile("mma.sync.aligned.m16n8k16.row.col.f32.f16.f16.f32 " \
                 "{%0,%1,%2,%3}, {%4,%5,%6,%7}, {%8,%9}, {%0,%1,%2,%3};" \
                 : "+f"((d)[0]), "+f"((d)[1]), "+f"((d)[2]), "+f"((d)[3]) \
                 : "r"((a)[0]), "r"((a)[1]), "r"((a)[2]), "r"((a)[3]), \
                   "r"((b)[0]), "r"((b)[1]))

// ---------------- setup: embed + W^T transpose + out zero + curl matrix ---------
__global__ __launch_bounds__(256) void setup_kernel(const float* __restrict__ inputs,
                                                    const float* __restrict__ Brff,
                                                    const float* __restrict__ Ws,
                                                    const float* __restrict__ Wf,
                                                    const float* __restrict__ scale,
                                                    float* __restrict__ out) {
    __shared__ float bsm[4 * 256];
    __shared__ float xs[32 * 4];
    __shared__ float tile[32][33];
    const int tid = threadIdx.x;

    if (blockIdx.x >= 4288) {
        // ---- curl head matrix: G[c][k][3] ----
        const float s0 = scale[0], s1 = scale[1], s2 = scale[2], s3 = scale[3];
        for (int k = tid; k < NN; k += 256) {
            const float w0 = Wf[k * 4 + 0] * s0, w1 = Wf[k * 4 + 1] * s1;
            const float w2 = Wf[k * 4 + 2] * s2, w3 = Wf[k * 4 + 3] * s3;
            // c=0: chan1 = dPdz -> u -= w1, v += w0, w += w3
            g_G[(0 * NN + k) * 3 + 0] = -w1;
            g_G[(0 * NN + k) * 3 + 1] =  w0;
            g_G[(0 * NN + k) * 3 + 2] =  w3;
            // c=1: chan2 = dPdx -> u += w3, v -= w2, w += w1
            g_G[(1 * NN + k) * 3 + 0] =  w3;
            g_G[(1 * NN + k) * 3 + 1] = -w2;
            g_G[(1 * NN + k) * 3 + 2] =  w1;
            // c=2: chan3 = dPdy -> u += w2, v += w3, w -= w0
            g_G[(2 * NN + k) * 3 + 0] =  w2;
            g_G[(2 * NN + k) * 3 + 1] =  w3;
            g_G[(2 * NN + k) * 3 + 2] = -w0;
        }
        return;
    }
    if (blockIdx.x >= 4096) {
        const int i = (blockIdx.x - 4096) * 1024 + tid * 4;   // < 196608
        *reinterpret_cast<float4*>(out + i) = make_float4(0.f, 0.f, 0.f, 0.f);
        return;
    }
    if (blockIdx.x >= 2048) {
        // ---- W^T transpose: g_Wt[l][n][k] = Ws[l][k][n], coalesced both sides ----
        const int bid = blockIdx.x - 2048;
        const int l = bid >> 8;
        const int t = bid & 255;
        const int k0 = (t >> 4) * 32, n0 = (t & 15) * 32;
        const float* src = Ws + ((size_t)l << 18);
        const int r = tid >> 5, c = tid & 31;
#pragma unroll
        for (int p = 0; p < 4; p++)
            tile[r + p * 8][c] = src[(size_t)(k0 + r + p * 8) * NN + (n0 + c)];
        __syncthreads();
        __half* dst = g_Wt + ((size_t)l << 18);
#pragma unroll
        for (int p = 0; p < 4; p++)
            dst[(size_t)(n0 + r + p * 8) * NN + (k0 + c)] =
                __float2half_rn(tile[c][r + p * 8]);
        return;
    }

    // ---- embed: RFF + tangent seeding ----
#pragma unroll
    for (int t = 0; t < 4; t++) bsm[t * 256 + tid] = Brff[t * 256 + tid];
    if (tid < 128) xs[tid] = inputs[(size_t)blockIdx.x * 128 + tid];
    __syncthreads();

    const int j = tid;
    const float b0 = bsm[j], b1 = bsm[256 + j], b2 = bsm[512 + j], b3 = bsm[768 + j];
#pragma unroll 1
    for (int it = 0; it < 32; it++) {
        float z = xs[it * 4 + 0] * b0 + xs[it * 4 + 1] * b1 +
                  xs[it * 4 + 2] * b2 + xs[it * 4 + 3] * b3;
        float sz, cz;
        __sincosf(z, &sz, &cz);
        size_t base = ((size_t)blockIdx.x * 32 + it) * NCH * NN;
        g_actA[base + j]            = __float2half_rn(sz);
        g_actA[base + 256 + j]      = __float2half_rn(cz);
        g_actA[base + 1 * NN + j]        = __float2half_rn(cz * b1);
        g_actA[base + 1 * NN + 256 + j]  = __float2half_rn(-sz * b1);
        g_actA[base + 2 * NN + j]        = __float2half_rn(cz * b2);
        g_actA[base + 2 * NN + 256 + j]  = __float2half_rn(-sz * b2);
        g_actA[base + 3 * NN + j]        = __float2half_rn(cz * b3);
        g_actA[base + 3 * NN + 256 + j]  = __float2half_rn(-sz * b3);
    }
}

// ---------------- fragment load helpers ----------------
__device__ __forceinline__ void load_a_frag(uint32_t a[2][4], uint32_t aB,
                                            int wm, int ks, int a_r, int a_c) {
#pragma unroll
    for (int mt = 0; mt < 2; mt++) {
        const int row = wm + mt * 16 + a_r;
        const uint32_t ad = aB + (uint32_t)((row * ASTRIDE + ks * 16 + a_c) * 2);
        LDM4(a[mt][0], a[mt][1], a[mt][2], a[mt][3], ad);
    }
}

__device__ __forceinline__ void load_b_frag(uint32_t b[8][2], uint32_t bB,
                                            int wn, int ks, int b_r, int b_c) {
#pragma unroll
    for (int bp = 0; bp < 4; bp++) {
        const int row = wn + bp * 16 + b_r;
        const uint32_t bd = bB + (uint32_t)((row * ASTRIDE + ks * 16 + b_c) * 2);
        uint32_t r0, r1, r2, r3;
        LDM4(r0, r1, r2, r3, bd);
        b[bp * 2][0] = r0;     b[bp * 2][1] = r2;
        b[bp * 2 + 1][0] = r1; b[bp * 2 + 1][1] = r3;
    }
}

// ---------------- shared GEMM mainloop (identical accumulation sequence) --------
__device__ __forceinline__ void gemm_mainloop(
    float d[2][8][4], const __half* __restrict__ Ain,
    const __half* __restrict__ Wl, uint32_t sbase,
    int m0, int n0, int tid, int lane, int wm, int wn) {

    const int lrow = tid >> 3, lseg = tid & 7;
    const __half* aptr = Ain + (size_t)(m0 + lrow) * NN + lseg * 8;
    const uint32_t adst = sbase + (uint32_t)(lrow * (ASTRIDE * 2) + lseg * 16);
    const __half* bptrs = Wl + (size_t)(n0 + lrow) * NN + lseg * 8;
    const uint32_t bdst = sbase + ASTAGE + (uint32_t)(lrow * (ASTRIDE * 2) + lseg * 16);

    {
        CP_ASYNC16(adst, aptr);
        CP_ASYNC16(adst + 32u * (ASTRIDE * 2), aptr + (size_t)32 * NN);
#pragma unroll
        for (int j = 0; j < 8; j++)
            CP_ASYNC16(bdst + (uint32_t)j * 32u * (ASTRIDE * 2),
                       bptrs + (size_t)j * 32 * NN);
        CP_COMMIT();
    }

    const int a_r = (lane & 15);
    const int a_c = (lane >> 4) * 8;
    const int b_r = (lane & 7) + (((lane >> 3) & 1) << 3);
    const int b_c = (lane >> 4) * 8;

    uint32_t afr[2][2][4];
    uint32_t bfr[2][8][2];

#pragma unroll
    for (int kt = 0; kt < KTILES; kt++) {
        CP_WAIT(0);
        __syncthreads();

        if (kt + 1 < KTILES) {
            const uint32_t so = ((kt + 1) & 1) * STAGE_BYTES;
            const size_t ko = (size_t)(kt + 1) * BK;
            CP_ASYNC16(adst + so, aptr + ko);
            CP_ASYNC16(adst + so + 32u * (ASTRIDE * 2), aptr + (size_t)32 * NN + ko);
#pragma unroll
            for (int j = 0; j < 8; j++)
                CP_ASYNC16(bdst + so + (uint32_t)j * 32u * (ASTRIDE * 2),
                           bptrs + (size_t)j * 32 * NN + ko);
            CP_COMMIT();
        }

        const uint32_t aB = sbase + (kt & 1) * STAGE_BYTES;
        const uint32_t bB = aB + ASTAGE;

        load_a_frag(afr[0], aB, wm, 0, a_r, a_c);
        load_b_frag(bfr[0], bB, wn, 0, b_r, b_c);
#pragma unroll
        for (int ks = 0; ks < 4; ks++) {
            const int cur = ks & 1, nxt = cur ^ 1;
            if (ks < 3) {
                load_a_frag(afr[nxt], aB, wm, ks + 1, a_r, a_c);
                load_b_frag(bfr[nxt], bB, wn, ks + 1, b_r, b_c);
            }
#pragma unroll
            for (int mt = 0; mt < 2; mt++)
#pragma unroll
                for (int nt = 0; nt < 8; nt++)
                    MMA16816(d[mt][nt], afr[cur][mt], bfr[cur][nt]);
        }
    }
}

// ---------------- mid layers 0..6: GEMM + branchless sin/cos JVP epilogue -------
__global__ __launch_bounds__(TPB, 2)
void layer_mid(int flip, int layer,
               const float* __restrict__ bs, const float* __restrict__ alphas) {
    const __half* __restrict__ Ain  = flip ? g_actB : g_actA;
    __half* __restrict__       Aout = flip ? g_actA : g_actB;
    const __half* __restrict__ Wl   = g_Wt + (size_t)layer * NN * NN;

    extern __shared__ __align__(128) char smem[];
    const uint32_t sbase = smem_u32(smem);
    const int tid = threadIdx.x, lane = tid & 31, wid = tid >> 5;
    const int m0 = blockIdx.y * BM, n0 = blockIdx.x * BN;
    const int wm = (wid >> 2) * 32;
    const int wn = (wid & 3) * 64;

    float d[2][8][4];
#pragma unroll
    for (int mt = 0; mt < 2; mt++)
#pragma unroll
        for (int nt = 0; nt < 8; nt++)
#pragma unroll
            for (int j = 0; j < 4; j++) d[mt][nt][j] = 0.f;

    gemm_mainloop(d, Ain, Wl, sbase, m0, n0, tid, lane, wm, wn);

    const float s = 1.0f + __ldg(alphas + layer);
    const float* __restrict__ bias = bs + layer * NN;
    const int chan = (lane >> 2) & 3;       // row % 4 (tile bases are multiples of 4)
    const int srclane = lane & ~12;         // lane holding the primal row's accum
    // branchless trig: primal lanes compute sin(q); tangent lanes cos(q)=sin(q+pi/2)
    const bool prim = (chan == 0);
    const float phase = prim ? 0.f : 1.5707963267948966f;

#pragma unroll
    for (int mt = 0; mt < 2; mt++) {
        const int r = m0 + wm + mt * 16 + (lane >> 2);
#pragma unroll
        for (int nt = 0; nt < 8; nt++) {
            const int c = n0 + wn + nt * 8 + (lane & 3) * 2;
            const float b0 = __ldg(bias + c), b1 = __ldg(bias + c + 1);
            const float v0 = d[mt][nt][0], v1 = d[mt][nt][1];
            const float v2 = d[mt][nt][2], v3 = d[mt][nt][3];
            const float p0 = __shfl_sync(0xffffffffu, v0, srclane);
            const float p1 = __shfl_sync(0xffffffffu, v1, srclane);
            const float p2 = __shfl_sync(0xffffffffu, v2, srclane);
            const float p3 = __shfl_sync(0xffffffffu, v3, srclane);
            const float t0 = __sinf((p0 + b0) * s + phase);
            const float t1 = __sinf((p1 + b1) * s + phase);
            const float t2 = __sinf((p2 + b0) * s + phase);
            const float t3 = __sinf((p3 + b1) * s + phase);
            const float o0 = prim ? t0 : s * v0 * t0;
            const float o1 = prim ? t1 : s * v1 * t1;
            const float o2 = prim ? t2 : s * v2 * t2;
            const float o3 = prim ? t3 : s * v3 * t3;
            *reinterpret_cast<__half2*>(Aout + (size_t)r * NN + c) =
                __floats2half2_rn(o0, o1);
            *reinterpret_cast<__half2*>(Aout + (size_t)(r + 8) * NN + c) =
                __floats2half2_rn(o2, o3);
        }
    }
}

// ---------------- last layer 7: GEMM + fused curl head -------------------------
__global__ __launch_bounds__(TPB, 2)
void layer_last(int flip, int layer,
                const float* __restrict__ bs, const float* __restrict__ alphas,
                float* __restrict__ out) {
    const __half* __restrict__ Ain = flip ? g_actB : g_actA;
    const __half* __restrict__ Wl  = g_Wt + (size_t)layer * NN * NN;

    extern __shared__ __align__(128) char smem[];
    const uint32_t sbase = smem_u32(smem);
    const int tid = threadIdx.x, lane = tid & 31, wid = tid >> 5;
    const int m0 = blockIdx.y * BM, n0 = blockIdx.x * BN;
    const int wm = (wid >> 2) * 32;
    const int wn = (wid & 3) * 64;

    float d[2][8][4];
#pragma unroll
    for (int mt = 0; mt < 2; mt++)
#pragma unroll
        for (int nt = 0; nt < 8; nt++)
#pragma unroll
            for (int j = 0; j < 4; j++) d[mt][nt][j] = 0.f;

    gemm_mainloop(d, Ain, Wl, sbase, m0, n0, tid, lane, wm, wn);

    const float s = 1.0f + __ldg(alphas + layer);
    const float* __restrict__ bias = bs + layer * NN;
    const int chan = (lane >> 2) & 3;
    const int srclane = lane & ~12;

    // ---- fused head: out += sum_k act_tangent * G  (curl pre-combined) ----
    float* sbuf = reinterpret_cast<float*>(smem);  // 64 rows x 3 floats
    __syncthreads();
    if (tid < 192) sbuf[tid] = 0.f;
    __syncthreads();

    const float* __restrict__ Gc =
        (chan > 0) ? (g_G + (size_t)(chan - 1) * NN * 3) : g_G;

#pragma unroll
    for (int mt = 0; mt < 2; mt++) {
        float part[2][3] = {{0.f, 0.f, 0.f}, {0.f, 0.f, 0.f}};
#pragma unroll
        for (int nt = 0; nt < 8; nt++) {
            const int c = n0 + wn + nt * 8 + (lane & 3) * 2;
            const float b0 = __ldg(bias + c), b1 = __ldg(bias + c + 1);
            const float v0 = d[mt][nt][0], v1 = d[mt][nt][1];
            const float v2 = d[mt][nt][2], v3 = d[mt][nt][3];
            const float p0 = __shfl_sync(0xffffffffu, v0, srclane);
            const float p1 = __shfl_sync(0xffffffffu, v1, srclane);
            const float p2 = __shfl_sync(0xffffffffu, v2, srclane);
            const float p3 = __shfl_sync(0xffffffffu, v3, srclane);
            if (chan != 0) {
                const float q0 = (p0 + b0) * s, q1 = (p1 + b1) * s;
                const float q2 = (p2 + b0) * s, q3 = (p3 + b1) * s;
                const float o0 = s * v0 * __cosf(q0);
                const float o1 = s * v1 * __cosf(q1);
                const float o2 = s * v2 * __cosf(q2);
                const float o3 = s * v3 * __cosf(q3);
                const float g00 = __ldg(Gc + (size_t)c * 3 + 0);
                const float g01 = __ldg(Gc + (size_t)c * 3 + 1);
                const float g02 = __ldg(Gc + (size_t)c * 3 + 2);
                const float g10 = __ldg(Gc + (size_t)(c + 1) * 3 + 0);
                const float g11 = __ldg(Gc + (size_t)(c + 1) * 3 + 1);
                const float g12 = __ldg(Gc + (size_t)(c + 1) * 3 + 2);
                part[0][0] += o0 * g00 + o1 * g10;
                part[0][1] += o0 * g01 + o1 * g11;
                part[0][2] += o0 * g02 + o1 * g12;
                part[1][0] += o2 * g00 + o3 * g10;
                part[1][1] += o2 * g01 + o3 * g11;
                part[1][2] += o2 * g02 + o3 * g12;
            }
        }
#pragma unroll
        for (int off = 1; off <= 2; off <<= 1)
#pragma unroll
            for (int h = 0; h < 2; h++)
#pragma unroll
                for (int j = 0; j < 3; j++)
                    part[h][j] += __shfl_xor_sync(0xffffffffu, part[h][j], off);
        if ((lane & 3) == 0 && chan != 0) {
            const int row0 = wm + mt * 16 + (lane >> 2);
#pragma unroll
            for (int j = 0; j < 3; j++) {
                atomicAdd(sbuf + row0 * 3 + j, part[0][j]);
                atomicAdd(sbuf + (row0 + 8) * 3 + j, part[1][j]);
            }
        }
    }
    __syncthreads();
    if (tid < 192) {
        const int row = tid / 3, j = tid - row * 3;
        if ((row & 3) != 0)
            atomicAdd(out + (size_t)((m0 + row) >> 2) * 3 + j, sbuf[row * 3 + j]);
    }
}

// ---------------- host launcher ----------------
extern "C" void kernel_launch(void* const* d_in, const int* in_sizes, int n_in,
                              void* d_out, int out_size) {
    const float* inputs = (const float*)d_in[0];  // [65536,4]
    const float* Brff   = (const float*)d_in[1];  // [4,256]
    const float* Ws     = (const float*)d_in[2];  // [8,512,512]
    const float* bs     = (const float*)d_in[3];  // [8,512]
    const float* alphas = (const float*)d_in[4];  // [9]
    const float* Wf     = (const float*)d_in[5];  // [512,4]
    const float* scale  = (const float*)d_in[6];  // [4]
    float* out = (float*)d_out;                   // [65536,3]

    cudaFuncSetAttribute(layer_mid, cudaFuncAttributeMaxDynamicSharedMemorySize,
                         SMEM_BYTES);
    cudaFuncSetAttribute(layer_last, cudaFuncAttributeMaxDynamicSharedMemorySize,
                         SMEM_BYTES);

    setup_kernel<<<4289, 256>>>(inputs, Brff, Ws, Wf, scale, out);
    dim3 grid(NN / BN, MTOT / BM);  // (2, 4096): x = n-tile for A L2 reuse
    for (int l = 0; l < NL - 1; l++)
        layer_mid<<<grid, TPB, SMEM_BYTES>>>(l & 1, l, bs, alphas);
    layer_last<<<grid, TPB, SMEM_BYTES>>>((NL - 1) & 1, NL - 1, bs, alphas, out);
}

// round 14
// speedup vs baseline: 1.0686x; 1.0016x over previous
#include <cuda_runtime.h>
#include <cuda_fp16.h>
#include <cstdint>

// ---------------- problem constants ----------------
#define BATCH   65536
#define NCH     4
#define MTOT    (BATCH*NCH)   // 262144 rows (sample-major, 4 channels interleaved)
#define NN      512
#define NL      8

// ---------------- GEMM tiling (R6 frozen: 2 CTAs/SM, 16 warps/SM) ---------------
#define BM      64
#define BN      256
#define BK      64
#define TPB     256
#define KTILES  (NN/BK)       // 8
#define ASTRIDE 72            // halves per smem row (64 + 8 pad), 144B
#define ASTAGE  (BM*ASTRIDE*2)        // 9216 B
#define BSTAGE  (BN*ASTRIDE*2)        // 36864 B
#define STAGE_BYTES (ASTAGE+BSTAGE)   // 46080 B
#define SMEM_BYTES  (STAGE_BYTES*2)   // 92160 B  (x2 CTAs = 184320 <= 227KB)

// ---------------- device scratch (no runtime allocation allowed) ----------------
__device__ __align__(256) __half g_actA[(size_t)MTOT * NN];   // 256 MB
__device__ __align__(256) __half g_actB[(size_t)MTOT * NN];   // 256 MB
__device__ __align__(256) __half g_Wt[(size_t)NL * NN * NN];  // W^T per layer, fp16
__device__ __align__(256) float  g_G[3 * NN * 3];             // curl-head matrix

// ---------------- PTX helpers (baseline compute_103 features ONLY) --------------
__device__ __forceinline__ uint32_t smem_u32(const void* p) {
    uint32_t a;
    asm("{ .reg .u64 t; cvta.to.shared.u64 t, %1; cvt.u32.u64 %0, t; }"
        : "=r"(a) : "l"(p));
    return a;
}

#define CP_ASYNC16(dst, src) \
    asm volatile("cp.async.cg.shared.global [%0], [%1], 16;" \
                 :: "r"(dst), "l"(src) : "memory")
#define CP_COMMIT() asm volatile("cp.async.commit_group;" ::: "memory")
#define CP_WAIT(n)  asm volatile("cp.async.wait_group %0;" :: "n"(n) : "memory")

#define LDM4(r0, r1, r2, r3, addr) \
    asm volatile("ldmatrix.sync.aligned.m8n8.x4.shared.b16 {%0,%1,%2,%3}, [%4];" \
                 : "=r"(r0), "=r"(r1), "=r"(r2), "=r"(r3) : "r"(addr))

#define MMA16816(d, a, b) \
    asm volatile("mma.sync.aligned.m16n8k16.row.col.f32.f16.f16.f32 " \
                 "{%0,%1,%2,%3}, {%4,%5,%6,%7}, {%8,%9}, {%0,%1,%2,%3};" \
                 : "+f"((d)[0]), "+f"((d)[1]), "+f"((d)[2]), "+f"((d)[3]) \
                 : "r"((a)[0]), "r"((a)[1]), "r"((a)[2]), "r"((a)[3]), \
                   "r"((b)[0]), "r"((b)[1]))

// ---------------- setup: embed + W^T transpose + out zero + curl matrix ---------
__global__ __launch_bounds__(256) void setup_kernel(const float* __restrict__ inputs,
                                                    const float* __restrict__ Brff,
                                                    const float* __restrict__ Ws,
                                                    const float* __restrict__ Wf,
                                                    const float* __restrict__ scale,
                                                    float* __restrict__ out) {
    __shared__ float bsm[4 * 256];
    __shared__ float xs[32 * 4];
    __shared__ float tile[32][33];
    const int tid = threadIdx.x;

    if (blockIdx.x >= 4288) {
        // ---- curl head matrix: G[c][k][3] ----
        const float s0 = scale[0], s1 = scale[1], s2 = scale[2], s3 = scale[3];
        for (int k = tid; k < NN; k += 256) {
            const float w0 = Wf[k * 4 + 0] * s0, w1 = Wf[k * 4 + 1] * s1;
            const float w2 = Wf[k * 4 + 2] * s2, w3 = Wf[k * 4 + 3] * s3;
            // c=0: chan1 = dPdz -> u -= w1, v += w0, w += w3
            g_G[(0 * NN + k) * 3 + 0] = -w1;
            g_G[(0 * NN + k) * 3 + 1] =  w0;
            g_G[(0 * NN + k) * 3 + 2] =  w3;
            // c=1: chan2 = dPdx -> u += w3, v -= w2, w += w1
            g_G[(1 * NN + k) * 3 + 0] =  w3;
            g_G[(1 * NN + k) * 3 + 1] = -w2;
            g_G[(1 * NN + k) * 3 + 2] =  w1;
            // c=2: chan3 = dPdy -> u += w2, v += w3, w -= w0
            g_G[(2 * NN + k) * 3 + 0] =  w2;
            g_G[(2 * NN + k) * 3 + 1] =  w3;
            g_G[(2 * NN + k) * 3 + 2] = -w0;
        }
        return;
    }
    if (blockIdx.x >= 4096) {
        const int i = (blockIdx.x - 4096) * 1024 + tid * 4;   // < 196608
        *reinterpret_cast<float4*>(out + i) = make_float4(0.f, 0.f, 0.f, 0.f);
        return;
    }
    if (blockIdx.x >= 2048) {
        // ---- W^T transpose: g_Wt[l][n][k] = Ws[l][k][n], coalesced both sides ----
        const int bid = blockIdx.x - 2048;
        const int l = bid >> 8;
        const int t = bid & 255;
        const int k0 = (t >> 4) * 32, n0 = (t & 15) * 32;
        const float* src = Ws + ((size_t)l << 18);
        const int r = tid >> 5, c = tid & 31;
#pragma unroll
        for (int p = 0; p < 4; p++)
            tile[r + p * 8][c] = src[(size_t)(k0 + r + p * 8) * NN + (n0 + c)];
        __syncthreads();
        __half* dst = g_Wt + ((size_t)l << 18);
#pragma unroll
        for (int p = 0; p < 4; p++)
            dst[(size_t)(n0 + r + p * 8) * NN + (k0 + c)] =
                __float2half_rn(tile[c][r + p * 8]);
        return;
    }

    // ---- embed: RFF + tangent seeding ----
#pragma unroll
    for (int t = 0; t < 4; t++) bsm[t * 256 + tid] = Brff[t * 256 + tid];
    if (tid < 128) xs[tid] = inputs[(size_t)blockIdx.x * 128 + tid];
    __syncthreads();

    const int j = tid;
    const float b0 = bsm[j], b1 = bsm[256 + j], b2 = bsm[512 + j], b3 = bsm[768 + j];
#pragma unroll 1
    for (int it = 0; it < 32; it++) {
        float z = xs[it * 4 + 0] * b0 + xs[it * 4 + 1] * b1 +
                  xs[it * 4 + 2] * b2 + xs[it * 4 + 3] * b3;
        float sz, cz;
        __sincosf(z, &sz, &cz);
        size_t base = ((size_t)blockIdx.x * 32 + it) * NCH * NN;
        g_actA[base + j]            = __float2half_rn(sz);
        g_actA[base + 256 + j]      = __float2half_rn(cz);
        g_actA[base + 1 * NN + j]        = __float2half_rn(cz * b1);
        g_actA[base + 1 * NN + 256 + j]  = __float2half_rn(-sz * b1);
        g_actA[base + 2 * NN + j]        = __float2half_rn(cz * b2);
        g_actA[base + 2 * NN + 256 + j]  = __float2half_rn(-sz * b2);
        g_actA[base + 3 * NN + j]        = __float2half_rn(cz * b3);
        g_actA[base + 3 * NN + 256 + j]  = __float2half_rn(-sz * b3);
    }
}

// ---------------- fragment load helpers ----------------
__device__ __forceinline__ void load_a_frag(uint32_t a[2][4], uint32_t aB,
                                            int wm, int ks, int a_r, int a_c) {
#pragma unroll
    for (int mt = 0; mt < 2; mt++) {
        const int row = wm + mt * 16 + a_r;
        const uint32_t ad = aB + (uint32_t)((row * ASTRIDE + ks * 16 + a_c) * 2);
        LDM4(a[mt][0], a[mt][1], a[mt][2], a[mt][3], ad);
    }
}

__device__ __forceinline__ void load_b_frag(uint32_t b[8][2], uint32_t bB,
                                            int wn, int ks, int b_r, int b_c) {
#pragma unroll
    for (int bp = 0; bp < 4; bp++) {
        const int row = wn + bp * 16 + b_r;
        const uint32_t bd = bB + (uint32_t)((row * ASTRIDE + ks * 16 + b_c) * 2);
        uint32_t r0, r1, r2, r3;
        LDM4(r0, r1, r2, r3, bd);
        b[bp * 2][0] = r0;     b[bp * 2][1] = r2;
        b[bp * 2 + 1][0] = r1; b[bp * 2 + 1][1] = r3;
    }
}

// ---------------- shared GEMM mainloop (identical accumulation sequence) --------
__device__ __forceinline__ void gemm_mainloop(
    float d[2][8][4], const __half* __restrict__ Ain,
    const __half* __restrict__ Wl, uint32_t sbase,
    int m0, int n0, int tid, int lane, int wm, int wn) {

    const int lrow = tid >> 3, lseg = tid & 7;
    const __half* aptr = Ain + (size_t)(m0 + lrow) * NN + lseg * 8;
    const uint32_t adst = sbase + (uint32_t)(lrow * (ASTRIDE * 2) + lseg * 16);
    const __half* bptrs = Wl + (size_t)(n0 + lrow) * NN + lseg * 8;
    const uint32_t bdst = sbase + ASTAGE + (uint32_t)(lrow * (ASTRIDE * 2) + lseg * 16);

    {
        CP_ASYNC16(adst, aptr);
        CP_ASYNC16(adst + 32u * (ASTRIDE * 2), aptr + (size_t)32 * NN);
#pragma unroll
        for (int j = 0; j < 8; j++)
            CP_ASYNC16(bdst + (uint32_t)j * 32u * (ASTRIDE * 2),
                       bptrs + (size_t)j * 32 * NN);
        CP_COMMIT();
    }

    const int a_r = (lane & 15);
    const int a_c = (lane >> 4) * 8;
    const int b_r = (lane & 7) + (((lane >> 3) & 1) << 3);
    const int b_c = (lane >> 4) * 8;

    uint32_t afr[2][2][4];
    uint32_t bfr[2][8][2];

#pragma unroll
    for (int kt = 0; kt < KTILES; kt++) {
        CP_WAIT(0);
        __syncthreads();

        if (kt + 1 < KTILES) {
            const uint32_t so = ((kt + 1) & 1) * STAGE_BYTES;
            const size_t ko = (size_t)(kt + 1) * BK;
            CP_ASYNC16(adst + so, aptr + ko);
            CP_ASYNC16(adst + so + 32u * (ASTRIDE * 2), aptr + (size_t)32 * NN + ko);
#pragma unroll
            for (int j = 0; j < 8; j++)
                CP_ASYNC16(bdst + so + (uint32_t)j * 32u * (ASTRIDE * 2),
                           bptrs + (size_t)j * 32 * NN + ko);
            CP_COMMIT();
        }

        const uint32_t aB = sbase + (kt & 1) * STAGE_BYTES;
        const uint32_t bB = aB + ASTAGE;

        load_a_frag(afr[0], aB, wm, 0, a_r, a_c);
        load_b_frag(bfr[0], bB, wn, 0, b_r, b_c);
#pragma unroll
        for (int ks = 0; ks < 4; ks++) {
            const int cur = ks & 1, nxt = cur ^ 1;
            if (ks < 3) {
                load_a_frag(afr[nxt], aB, wm, ks + 1, a_r, a_c);
                load_b_frag(bfr[nxt], bB, wn, ks + 1, b_r, b_c);
            }
#pragma unroll
            for (int mt = 0; mt < 2; mt++)
#pragma unroll
                for (int nt = 0; nt < 8; nt++)
                    MMA16816(d[mt][nt], afr[cur][mt], bfr[cur][nt]);
        }
    }
}

// ---------------- mid layers 0..6: GEMM + branchless sin/cos JVP epilogue -------
__global__ __launch_bounds__(TPB, 2)
void layer_mid(int flip, int layer,
               const float* __restrict__ bs, const float* __restrict__ alphas) {
    const __half* __restrict__ Ain  = flip ? g_actB : g_actA;
    __half* __restrict__       Aout = flip ? g_actA : g_actB;
    const __half* __restrict__ Wl   = g_Wt + (size_t)layer * NN * NN;

    extern __shared__ __align__(128) char smem[];
    const uint32_t sbase = smem_u32(smem);
    const int tid = threadIdx.x, lane = tid & 31, wid = tid >> 5;
    const int m0 = blockIdx.y * BM, n0 = blockIdx.x * BN;
    const int wm = (wid >> 2) * 32;
    const int wn = (wid & 3) * 64;

    float d[2][8][4];
#pragma unroll
    for (int mt = 0; mt < 2; mt++)
#pragma unroll
        for (int nt = 0; nt < 8; nt++)
#pragma unroll
            for (int j = 0; j < 4; j++) d[mt][nt][j] = 0.f;

    gemm_mainloop(d, Ain, Wl, sbase, m0, n0, tid, lane, wm, wn);

    const float s = 1.0f + __ldg(alphas + layer);
    const float* __restrict__ bias = bs + layer * NN;
    const int chan = (lane >> 2) & 3;       // row % 4 (tile bases are multiples of 4)
    const int srclane = lane & ~12;         // lane holding the primal row's accum
    // branchless trig: primal lanes compute sin(q); tangent lanes cos(q)=sin(q+pi/2)
    const bool prim = (chan == 0);
    const float phase = prim ? 0.f : 1.5707963267948966f;

    // hoisted bias loads: c depends only on nt (halves epilogue LDG count)
    float bb[8][2];
#pragma unroll
    for (int nt = 0; nt < 8; nt++) {
        const int c = n0 + wn + nt * 8 + (lane & 3) * 2;
        bb[nt][0] = __ldg(bias + c);
        bb[nt][1] = __ldg(bias + c + 1);
    }

#pragma unroll
    for (int mt = 0; mt < 2; mt++) {
        const int r = m0 + wm + mt * 16 + (lane >> 2);
#pragma unroll
        for (int nt = 0; nt < 8; nt++) {
            const int c = n0 + wn + nt * 8 + (lane & 3) * 2;
            const float b0 = bb[nt][0], b1 = bb[nt][1];
            const float v0 = d[mt][nt][0], v1 = d[mt][nt][1];
            const float v2 = d[mt][nt][2], v3 = d[mt][nt][3];
            const float p0 = __shfl_sync(0xffffffffu, v0, srclane);
            const float p1 = __shfl_sync(0xffffffffu, v1, srclane);
            const float p2 = __shfl_sync(0xffffffffu, v2, srclane);
            const float p3 = __shfl_sync(0xffffffffu, v3, srclane);
            const float t0 = __sinf((p0 + b0) * s + phase);
            const float t1 = __sinf((p1 + b1) * s + phase);
            const float t2 = __sinf((p2 + b0) * s + phase);
            const float t3 = __sinf((p3 + b1) * s + phase);
            const float o0 = prim ? t0 : s * v0 * t0;
            const float o1 = prim ? t1 : s * v1 * t1;
            const float o2 = prim ? t2 : s * v2 * t2;
            const float o3 = prim ? t3 : s * v3 * t3;
            *reinterpret_cast<__half2*>(Aout + (size_t)r * NN + c) =
                __floats2half2_rn(o0, o1);
            *reinterpret_cast<__half2*>(Aout + (size_t)(r + 8) * NN + c) =
                __floats2half2_rn(o2, o3);
        }
    }
}

// ---------------- last layer 7: GEMM + fused curl head -------------------------
__global__ __launch_bounds__(TPB, 2)
void layer_last(int flip, int layer,
                const float* __restrict__ bs, const float* __restrict__ alphas,
                float* __restrict__ out) {
    const __half* __restrict__ Ain = flip ? g_actB : g_actA;
    const __half* __restrict__ Wl  = g_Wt + (size_t)layer * NN * NN;

    extern __shared__ __align__(128) char smem[];
    const uint32_t sbase = smem_u32(smem);
    const int tid = threadIdx.x, lane = tid & 31, wid = tid >> 5;
    const int m0 = blockIdx.y * BM, n0 = blockIdx.x * BN;
    const int wm = (wid >> 2) * 32;
    const int wn = (wid & 3) * 64;

    float d[2][8][4];
#pragma unroll
    for (int mt = 0; mt < 2; mt++)
#pragma unroll
        for (int nt = 0; nt < 8; nt++)
#pragma unroll
            for (int j = 0; j < 4; j++) d[mt][nt][j] = 0.f;

    gemm_mainloop(d, Ain, Wl, sbase, m0, n0, tid, lane, wm, wn);

    const float s = 1.0f + __ldg(alphas + layer);
    const float* __restrict__ bias = bs + layer * NN;
    const int chan = (lane >> 2) & 3;
    const int srclane = lane & ~12;

    // ---- fused head: out += sum_k act_tangent * G  (curl pre-combined) ----
    float* sbuf = reinterpret_cast<float*>(smem);  // 64 rows x 3 floats
    __syncthreads();
    if (tid < 192) sbuf[tid] = 0.f;
    __syncthreads();

    const float* __restrict__ Gc =
        (chan > 0) ? (g_G + (size_t)(chan - 1) * NN * 3) : g_G;

#pragma unroll
    for (int mt = 0; mt < 2; mt++) {
        float part[2][3] = {{0.f, 0.f, 0.f}, {0.f, 0.f, 0.f}};
#pragma unroll
        for (int nt = 0; nt < 8; nt++) {
            const int c = n0 + wn + nt * 8 + (lane & 3) * 2;
            const float b0 = __ldg(bias + c), b1 = __ldg(bias + c + 1);
            const float v0 = d[mt][nt][0], v1 = d[mt][nt][1];
            const float v2 = d[mt][nt][2], v3 = d[mt][nt][3];
            const float p0 = __shfl_sync(0xffffffffu, v0, srclane);
            const float p1 = __shfl_sync(0xffffffffu, v1, srclane);
            const float p2 = __shfl_sync(0xffffffffu, v2, srclane);
            const float p3 = __shfl_sync(0xffffffffu, v3, srclane);
            if (chan != 0) {
                const float q0 = (p0 + b0) * s, q1 = (p1 + b1) * s;
                const float q2 = (p2 + b0) * s, q3 = (p3 + b1) * s;
                const float o0 = s * v0 * __cosf(q0);
                const float o1 = s * v1 * __cosf(q1);
                const float o2 = s * v2 * __cosf(q2);
                const float o3 = s * v3 * __cosf(q3);
                const float g00 = __ldg(Gc + (size_t)c * 3 + 0);
                const float g01 = __ldg(Gc + (size_t)c * 3 + 1);
                const float g02 = __ldg(Gc + (size_t)c * 3 + 2);
                const float g10 = __ldg(Gc + (size_t)(c + 1) * 3 + 0);
                const float g11 = __ldg(Gc + (size_t)(c + 1) * 3 + 1);
                const float g12 = __ldg(Gc + (size_t)(c + 1) * 3 + 2);
                part[0][0] += o0 * g00 + o1 * g10;
                part[0][1] += o0 * g01 + o1 * g11;
                part[0][2] += o0 * g02 + o1 * g12;
                part[1][0] += o2 * g00 + o3 * g10;
                part[1][1] += o2 * g01 + o3 * g11;
                part[1][2] += o2 * g02 + o3 * g12;
            }
        }
#pragma unroll
        for (int off = 1; off <= 2; off <<= 1)
#pragma unroll
            for (int h = 0; h < 2; h++)
#pragma unroll
                for (int j = 0; j < 3; j++)
                    part[h][j] += __shfl_xor_sync(0xffffffffu, part[h][j], off);
        if ((lane & 3) == 0 && chan != 0) {
            const int row0 = wm + mt * 16 + (lane >> 2);
#pragma unroll
            for (int j = 0; j < 3; j++) {
                atomicAdd(sbuf + row0 * 3 + j, part[0][j]);
                atomicAdd(sbuf + (row0 + 8) * 3 + j, part[1][j]);
            }
        }
    }
    __syncthreads();
    if (tid < 192) {
        const int row = tid / 3, j = tid - row * 3;
        if ((row & 3) != 0)
            atomicAdd(out + (size_t)((m0 + row) >> 2) * 3 + j, sbuf[row * 3 + j]);
    }
}

// ---------------- host launcher ----------------
extern "C" void kernel_launch(void* const* d_in, const int* in_sizes, int n_in,
                              void* d_out, int out_size) {
    const float* inputs = (const float*)d_in[0];  // [65536,4]
    const float* Brff   = (const float*)d_in[1];  // [4,256]
    const float* Ws     = (const float*)d_in[2];  // [8,512,512]
    const float* bs     = (const float*)d_in[3];  // [8,512]
    const float* alphas = (const float*)d_in[4];  // [9]
    const float* Wf     = (const float*)d_in[5];  // [512,4]
    const float* scale  = (const float*)d_in[6];  // [4]
    float* out = (float*)d_out;                   // [65536,3]

    cudaFuncSetAttribute(layer_mid, cudaFuncAttributeMaxDynamicSharedMemorySize,
                         SMEM_BYTES);
    cudaFuncSetAttribute(layer_last, cudaFuncAttributeMaxDynamicSharedMemorySize,
                         SMEM_BYTES);

    setup_kernel<<<4289, 256>>>(inputs, Brff, Ws, Wf, scale, out);
    dim3 grid(NN / BN, MTOT / BM);  // (2, 4096): x = n-tile for A L2 reuse
    for (int l = 0; l < NL - 1; l++)
        layer_mid<<<grid, TPB, SMEM_BYTES>>>(l & 1, l, bs, alphas);
    layer_last<<<grid, TPB, SMEM_BYTES>>>((NL - 1) & 1, NL - 1, bs, alphas, out);
}